// round 3
// baseline (speedup 1.0000x reference)
#include <cuda_runtime.h>
#include <cuda_bf16.h>
#include <cstdint>

// Problem constants
#define Bn 512
#define Sn 512
#define Dn 512
#define LN_EPS 1e-5f

// Scratch (no allocations allowed)
__device__ float g_info[Bn * Dn];      // embeded_info [B, D]  (1 MB)
__device__ int   g_rowoff[Bn];         // exclusive prefix of per-row sentinel counts

// ---------------------------------------------------------------------------
// Kernel 1: embeded_info = concat(LN(scores)@Ws+bs, oya_e, dora_e, hrs@Wh+bh) @ W_info + b_info
// Tiling: block = 8 batch rows x 128 output cols, blockDim = 128.
// grid = (Dn/128, Bn/8) = (4, 64) = 256 blocks.
// ---------------------------------------------------------------------------
__global__ __launch_bounds__(128) void kernel_info(
    const float* __restrict__ scores,      // [B,4]
    const int*   __restrict__ oya,         // [B]
    const int*   __restrict__ dora,        // [B,5]
    const float* __restrict__ hrs,         // [B,2]
    const float* __restrict__ oya_table,   // [4,16]
    const float* __restrict__ dora_table,  // [38,64]
    const float* __restrict__ ln_gamma,    // [4]
    const float* __restrict__ ln_beta,     // [4]
    const float* __restrict__ W_scores,    // [4,32]
    const float* __restrict__ b_scores,    // [32]
    const float* __restrict__ W_hrs,       // [2,16]
    const float* __restrict__ b_hrs,       // [16]
    const float* __restrict__ W_info,      // [384,512]
    const float* __restrict__ b_info)      // [512]
{
    __shared__ float csh[8 * 384];   // concat rows, 12 KB

    const int tid = threadIdx.x;
    const int b0  = blockIdx.y * 8;

    // Build the 8 concat rows (384 wide) cooperatively.
    for (int r = 0; r < 8; ++r) {
        const int b = b0 + r;
        // LayerNorm of 4 scores (redundant per thread; trivial, broadcast loads)
        float s0 = scores[b * 4 + 0], s1 = scores[b * 4 + 1];
        float s2 = scores[b * 4 + 2], s3 = scores[b * 4 + 3];
        float mu  = 0.25f * (s0 + s1 + s2 + s3);
        float d0 = s0 - mu, d1 = s1 - mu, d2 = s2 - mu, d3 = s3 - mu;
        float var = 0.25f * (d0 * d0 + d1 * d1 + d2 * d2 + d3 * d3);
        float rstd = rsqrtf(var + LN_EPS);
        float n0 = d0 * rstd * ln_gamma[0] + ln_beta[0];
        float n1 = d1 * rstd * ln_gamma[1] + ln_beta[1];
        float n2 = d2 * rstd * ln_gamma[2] + ln_beta[2];
        float n3 = d3 * rstd * ln_gamma[3] + ln_beta[3];

        for (int kk = tid; kk < 384; kk += 128) {
            float v;
            if (kk < 32) {
                v = b_scores[kk]
                  + n0 * W_scores[0 * 32 + kk] + n1 * W_scores[1 * 32 + kk]
                  + n2 * W_scores[2 * 32 + kk] + n3 * W_scores[3 * 32 + kk];
            } else if (kk < 48) {
                v = oya_table[oya[b] * 16 + (kk - 32)];
            } else if (kk < 368) {
                int j = (kk - 48) >> 6;
                int c = (kk - 48) & 63;
                v = dora_table[dora[b * 5 + j] * 64 + c];
            } else {
                int c = kk - 368;
                v = b_hrs[c] + hrs[b * 2 + 0] * W_hrs[0 * 16 + c]
                             + hrs[b * 2 + 1] * W_hrs[1 * 16 + c];
            }
            csh[r * 384 + kk] = v;
        }
    }
    __syncthreads();

    // GEMM: each thread owns one output column c, accumulates 8 rows.
    const int c = blockIdx.x * 128 + tid;
    float acc[8];
#pragma unroll
    for (int r = 0; r < 8; ++r) acc[r] = 0.f;

    const float4* csh4 = reinterpret_cast<const float4*>(csh);  // row stride = 96 float4
#pragma unroll 4
    for (int k4 = 0; k4 < 96; ++k4) {
        float cf[8][4];
#pragma unroll
        for (int r = 0; r < 8; ++r) {
            float4 q = csh4[r * 96 + k4];
            cf[r][0] = q.x; cf[r][1] = q.y; cf[r][2] = q.z; cf[r][3] = q.w;
        }
#pragma unroll
        for (int kk = 0; kk < 4; ++kk) {
            float w = W_info[(k4 * 4 + kk) * Dn + c];
#pragma unroll
            for (int r = 0; r < 8; ++r) acc[r] += cf[r][kk] * w;
        }
    }

    float bi = b_info[c];
#pragma unroll
    for (int r = 0; r < 8; ++r)
        g_info[(b0 + r) * Dn + c] = acc[r] + bi;
}

// ---------------------------------------------------------------------------
// Kernel 2: per-row sentinel count + exclusive scan (single block, 512 threads)
// ---------------------------------------------------------------------------
__global__ __launch_bounds__(Bn) void kernel_rowoff(const int* __restrict__ action)
{
    __shared__ int sh[Bn];
    const int b = threadIdx.x;
    int cnt = 0;
    for (int s = 0; s < Sn; ++s)
        cnt += (action[b * Sn + s] == 224);
    sh[b] = cnt;
    __syncthreads();
    // Hillis–Steele inclusive scan
    for (int off = 1; off < Bn; off <<= 1) {
        int v = (b >= off) ? sh[b - off] : 0;
        __syncthreads();
        sh[b] += v;
        __syncthreads();
    }
    g_rowoff[b] = sh[b] - cnt;   // exclusive
}

// ---------------------------------------------------------------------------
// Kernel 3: bulk gather-copy (the 537 MB write). Writes ALL positions from
// action_table (sentinel rows use table[224], overwritten by kernel 4).
// 8 independent float4 per thread (MLP_p1=8) to cover L2 gather latency.
// Streaming stores (__stcs) keep the write stream from evicting the
// L2-resident action_table.
// ---------------------------------------------------------------------------
#define MAIN_TPB 256
#define MAIN_VPT 8
__global__ __launch_bounds__(MAIN_TPB) void kernel_main(
    const int*   __restrict__ action,       // [B*S]
    const float* __restrict__ action_table, // [225, 512]
    float*       __restrict__ out)          // [B*S*D]
{
    const int stride = gridDim.x * MAIN_TPB;           // = n4 / MAIN_VPT
    int idx = blockIdx.x * MAIN_TPB + threadIdx.x;
    const float4* tbl4 = reinterpret_cast<const float4*>(action_table);
    float4*       out4 = reinterpret_cast<float4*>(out);

    int    id[MAIN_VPT];
    float4 v[MAIN_VPT];
#pragma unroll
    for (int i = 0; i < MAIN_VPT; ++i) {
        id[i] = idx + i * stride;
        int bs = id[i] >> 7;          // /128 float4 per (b,s)
        int d4 = id[i] & 127;
        int a  = __ldg(&action[bs]);
        v[i] = __ldg(&tbl4[a * 128 + d4]);
    }
#pragma unroll
    for (int i = 0; i < MAIN_VPT; ++i)
        __stcs(&out4[id[i]], v[i]);
}

// ---------------------------------------------------------------------------
// Kernel 4: scatter embeded_info into sentinel positions (after kernel 3).
// One block per batch row; in-block ordered scan finds sentinel positions.
// ---------------------------------------------------------------------------
__global__ __launch_bounds__(128) void kernel_scatter(
    const int* __restrict__ action,
    float*     __restrict__ out)
{
    __shared__ int spos[Sn];
    __shared__ int sh[128];
    const int b = blockIdx.x;
    const int t = threadIdx.x;

    // thread t owns contiguous s in [4t, 4t+4) so scan order == s order
    int f[4];
    int cnt = 0;
#pragma unroll
    for (int j = 0; j < 4; ++j) {
        f[j] = (action[b * Sn + 4 * t + j] == 224);
        cnt += f[j];
    }
    sh[t] = cnt;
    __syncthreads();
    for (int off = 1; off < 128; off <<= 1) {
        int v = (t >= off) ? sh[t - off] : 0;
        __syncthreads();
        sh[t] += v;
        __syncthreads();
    }
    int o = sh[t] - cnt;   // exclusive
#pragma unroll
    for (int j = 0; j < 4; ++j) {
        if (f[j]) spos[o++] = 4 * t + j;
    }
    __syncthreads();
    const int total = sh[127];
    const int ro    = g_rowoff[b];

    const float4* info4 = reinterpret_cast<const float4*>(g_info);
    float4*       out4  = reinterpret_cast<float4*>(out);
    for (int i = 0; i < total; ++i) {
        int s   = spos[i];
        int occ = ro + i;
        occ = occ < (Bn - 1) ? occ : (Bn - 1);   // clip (occ at a sentinel is always >= 0)
        out4[(b * Sn + s) * 128 + t] = info4[occ * 128 + t];
    }
}

// ---------------------------------------------------------------------------
// Launch
// Input order (metadata): scores, oya, dora, honba_riichi_sticks, action, mask,
//   action_table, oya_table, dora_table, ln_gamma, ln_beta, W_scores, b_scores,
//   W_hrs, b_hrs, W_info, b_info
// ---------------------------------------------------------------------------
extern "C" void kernel_launch(void* const* d_in, const int* in_sizes, int n_in,
                              void* d_out, int out_size)
{
    const float* scores       = (const float*)d_in[0];
    const int*   oya          = (const int*)  d_in[1];
    const int*   dora         = (const int*)  d_in[2];
    const float* hrs          = (const float*)d_in[3];
    const int*   action       = (const int*)  d_in[4];
    /* mask d_in[5] unused */
    const float* action_table = (const float*)d_in[6];
    const float* oya_table    = (const float*)d_in[7];
    const float* dora_table   = (const float*)d_in[8];
    const float* ln_gamma     = (const float*)d_in[9];
    const float* ln_beta      = (const float*)d_in[10];
    const float* W_scores     = (const float*)d_in[11];
    const float* b_scores     = (const float*)d_in[12];
    const float* W_hrs        = (const float*)d_in[13];
    const float* b_hrs        = (const float*)d_in[14];
    const float* W_info       = (const float*)d_in[15];
    const float* b_info       = (const float*)d_in[16];
    float* out = (float*)d_out;

    dim3 gi(Dn / 128, Bn / 8);
    kernel_info<<<gi, 128>>>(scores, oya, dora, hrs, oya_table, dora_table,
                             ln_gamma, ln_beta, W_scores, b_scores,
                             W_hrs, b_hrs, W_info, b_info);

    kernel_rowoff<<<1, Bn>>>(action);

    const int n4   = Bn * Sn * (Dn / 4);
    const int grid = n4 / (MAIN_TPB * MAIN_VPT);   // 16384
    kernel_main<<<grid, MAIN_TPB>>>(action, action_table, out);

    kernel_scatter<<<Bn, 128>>>(action, out);
}

// round 4
// speedup vs baseline: 2.1206x; 2.1206x over previous
#include <cuda_runtime.h>
#include <cuda_bf16.h>
#include <cstdint>

// Problem constants
#define Bn 512
#define Sn 512
#define Dn 512
#define LN_EPS 1e-5f

// Scratch (no allocations allowed)
__device__ float g_info[Bn * Dn];      // embeded_info [B, D]  (1 MB)
__device__ int   g_cnt[Bn];            // per-row sentinel counts
__device__ int   g_rowoff[Bn];         // exclusive prefix of per-row sentinel counts

// ---------------------------------------------------------------------------
// Kernel 1: embeded_info = concat(LN(scores)@Ws+bs, oya_e, dora_e, hrs@Wh+bh) @ W_info + b_info
// Tiling: block = 8 batch rows x 128 output cols, blockDim = 128.
// grid = (Dn/128, Bn/8) = (4, 64) = 256 blocks.
// ---------------------------------------------------------------------------
__global__ __launch_bounds__(128) void kernel_info(
    const float* __restrict__ scores,      // [B,4]
    const int*   __restrict__ oya,         // [B]
    const int*   __restrict__ dora,        // [B,5]
    const float* __restrict__ hrs,         // [B,2]
    const float* __restrict__ oya_table,   // [4,16]
    const float* __restrict__ dora_table,  // [38,64]
    const float* __restrict__ ln_gamma,    // [4]
    const float* __restrict__ ln_beta,     // [4]
    const float* __restrict__ W_scores,    // [4,32]
    const float* __restrict__ b_scores,    // [32]
    const float* __restrict__ W_hrs,       // [2,16]
    const float* __restrict__ b_hrs,       // [16]
    const float* __restrict__ W_info,      // [384,512]
    const float* __restrict__ b_info)      // [512]
{
    __shared__ float csh[8 * 384];   // concat rows, 12 KB

    const int tid = threadIdx.x;
    const int b0  = blockIdx.y * 8;

    // Build the 8 concat rows (384 wide) cooperatively.
    for (int r = 0; r < 8; ++r) {
        const int b = b0 + r;
        // LayerNorm of 4 scores (redundant per thread; trivial, broadcast loads)
        float s0 = scores[b * 4 + 0], s1 = scores[b * 4 + 1];
        float s2 = scores[b * 4 + 2], s3 = scores[b * 4 + 3];
        float mu  = 0.25f * (s0 + s1 + s2 + s3);
        float d0 = s0 - mu, d1 = s1 - mu, d2 = s2 - mu, d3 = s3 - mu;
        float var = 0.25f * (d0 * d0 + d1 * d1 + d2 * d2 + d3 * d3);
        float rstd = rsqrtf(var + LN_EPS);
        float n0 = d0 * rstd * ln_gamma[0] + ln_beta[0];
        float n1 = d1 * rstd * ln_gamma[1] + ln_beta[1];
        float n2 = d2 * rstd * ln_gamma[2] + ln_beta[2];
        float n3 = d3 * rstd * ln_gamma[3] + ln_beta[3];

        for (int kk = tid; kk < 384; kk += 128) {
            float v;
            if (kk < 32) {
                v = b_scores[kk]
                  + n0 * W_scores[0 * 32 + kk] + n1 * W_scores[1 * 32 + kk]
                  + n2 * W_scores[2 * 32 + kk] + n3 * W_scores[3 * 32 + kk];
            } else if (kk < 48) {
                v = oya_table[oya[b] * 16 + (kk - 32)];
            } else if (kk < 368) {
                int j = (kk - 48) >> 6;
                int c = (kk - 48) & 63;
                v = dora_table[dora[b * 5 + j] * 64 + c];
            } else {
                int c = kk - 368;
                v = b_hrs[c] + hrs[b * 2 + 0] * W_hrs[0 * 16 + c]
                             + hrs[b * 2 + 1] * W_hrs[1 * 16 + c];
            }
            csh[r * 384 + kk] = v;
        }
    }
    __syncthreads();

    // GEMM: each thread owns one output column c, accumulates 8 rows.
    const int c = blockIdx.x * 128 + tid;
    float acc[8];
#pragma unroll
    for (int r = 0; r < 8; ++r) acc[r] = 0.f;

    const float4* csh4 = reinterpret_cast<const float4*>(csh);  // row stride = 96 float4
#pragma unroll 4
    for (int k4 = 0; k4 < 96; ++k4) {
        float cf[8][4];
#pragma unroll
        for (int r = 0; r < 8; ++r) {
            float4 q = csh4[r * 96 + k4];
            cf[r][0] = q.x; cf[r][1] = q.y; cf[r][2] = q.z; cf[r][3] = q.w;
        }
#pragma unroll
        for (int kk = 0; kk < 4; ++kk) {
            float w = W_info[(k4 * 4 + kk) * Dn + c];
#pragma unroll
            for (int r = 0; r < 8; ++r) acc[r] += cf[r][kk] * w;
        }
    }

    float bi = b_info[c];
#pragma unroll
    for (int r = 0; r < 8; ++r)
        g_info[(b0 + r) * Dn + c] = acc[r] + bi;
}

// ---------------------------------------------------------------------------
// Kernel 2a: per-row sentinel count, COALESCED. One block per batch row,
// thread t reads s = t, t+128, t+256, t+384 (warp-contiguous addresses).
// ---------------------------------------------------------------------------
__global__ __launch_bounds__(128) void kernel_count(const int* __restrict__ action)
{
    __shared__ int wsum[4];
    const int b = blockIdx.x;
    const int t = threadIdx.x;
    int cnt = 0;
#pragma unroll
    for (int j = 0; j < 4; ++j)
        cnt += (action[b * Sn + t + j * 128] == 224);
    // warp reduce
#pragma unroll
    for (int off = 16; off > 0; off >>= 1)
        cnt += __shfl_down_sync(0xffffffffu, cnt, off);
    if ((t & 31) == 0) wsum[t >> 5] = cnt;
    __syncthreads();
    if (t == 0) g_cnt[b] = wsum[0] + wsum[1] + wsum[2] + wsum[3];
}

// ---------------------------------------------------------------------------
// Kernel 2b: exclusive scan of 512 counts (single block, trivial).
// ---------------------------------------------------------------------------
__global__ __launch_bounds__(Bn) void kernel_scan()
{
    __shared__ int sh[Bn];
    const int b = threadIdx.x;
    const int c = g_cnt[b];
    sh[b] = c;
    __syncthreads();
    for (int off = 1; off < Bn; off <<= 1) {
        int v = (b >= off) ? sh[b - off] : 0;
        __syncthreads();
        sh[b] += v;
        __syncthreads();
    }
    g_rowoff[b] = sh[b] - c;   // exclusive
}

// ---------------------------------------------------------------------------
// Kernel 3: bulk gather-copy (the 537 MB write). Writes ALL positions from
// action_table (sentinel rows use table[224], overwritten by kernel 4).
// 8 independent float4 per thread (MLP_p1=8) to cover L2 gather latency.
// Streaming stores (__stcs) keep the write stream from evicting the
// L2-resident action_table.
// ---------------------------------------------------------------------------
#define MAIN_TPB 256
#define MAIN_VPT 8
__global__ __launch_bounds__(MAIN_TPB) void kernel_main(
    const int*   __restrict__ action,       // [B*S]
    const float* __restrict__ action_table, // [225, 512]
    float*       __restrict__ out)          // [B*S*D]
{
    const int stride = gridDim.x * MAIN_TPB;           // = n4 / MAIN_VPT
    int idx = blockIdx.x * MAIN_TPB + threadIdx.x;
    const float4* tbl4 = reinterpret_cast<const float4*>(action_table);
    float4*       out4 = reinterpret_cast<float4*>(out);

    int    id[MAIN_VPT];
    float4 v[MAIN_VPT];
#pragma unroll
    for (int i = 0; i < MAIN_VPT; ++i) {
        id[i] = idx + i * stride;
        int bs = id[i] >> 7;          // /128 float4 per (b,s)
        int d4 = id[i] & 127;
        int a  = __ldg(&action[bs]);
        v[i] = __ldg(&tbl4[a * 128 + d4]);
    }
#pragma unroll
    for (int i = 0; i < MAIN_VPT; ++i)
        __stcs(&out4[id[i]], v[i]);
}

// ---------------------------------------------------------------------------
// Kernel 4: scatter embeded_info into sentinel positions (after kernel 3).
// One block per batch row; in-block ordered scan finds sentinel positions.
// ---------------------------------------------------------------------------
__global__ __launch_bounds__(128) void kernel_scatter(
    const int* __restrict__ action,
    float*     __restrict__ out)
{
    __shared__ int spos[Sn];
    __shared__ int sh[128];
    const int b = blockIdx.x;
    const int t = threadIdx.x;

    // thread t owns contiguous s in [4t, 4t+4) so scan order == s order
    int f[4];
    int cnt = 0;
#pragma unroll
    for (int j = 0; j < 4; ++j) {
        f[j] = (action[b * Sn + 4 * t + j] == 224);
        cnt += f[j];
    }
    sh[t] = cnt;
    __syncthreads();
    for (int off = 1; off < 128; off <<= 1) {
        int v = (t >= off) ? sh[t - off] : 0;
        __syncthreads();
        sh[t] += v;
        __syncthreads();
    }
    int o = sh[t] - cnt;   // exclusive
#pragma unroll
    for (int j = 0; j < 4; ++j) {
        if (f[j]) spos[o++] = 4 * t + j;
    }
    __syncthreads();
    const int total = sh[127];
    const int ro    = g_rowoff[b];

    const float4* info4 = reinterpret_cast<const float4*>(g_info);
    float4*       out4  = reinterpret_cast<float4*>(out);
    for (int i = 0; i < total; ++i) {
        int s   = spos[i];
        int occ = ro + i;
        occ = occ < (Bn - 1) ? occ : (Bn - 1);   // clip (occ at a sentinel is always >= 0)
        out4[(b * Sn + s) * 128 + t] = info4[occ * 128 + t];
    }
}

// ---------------------------------------------------------------------------
// Launch
// Input order (metadata): scores, oya, dora, honba_riichi_sticks, action, mask,
//   action_table, oya_table, dora_table, ln_gamma, ln_beta, W_scores, b_scores,
//   W_hrs, b_hrs, W_info, b_info
// ---------------------------------------------------------------------------
extern "C" void kernel_launch(void* const* d_in, const int* in_sizes, int n_in,
                              void* d_out, int out_size)
{
    const float* scores       = (const float*)d_in[0];
    const int*   oya          = (const int*)  d_in[1];
    const int*   dora         = (const int*)  d_in[2];
    const float* hrs          = (const float*)d_in[3];
    const int*   action       = (const int*)  d_in[4];
    /* mask d_in[5] unused */
    const float* action_table = (const float*)d_in[6];
    const float* oya_table    = (const float*)d_in[7];
    const float* dora_table   = (const float*)d_in[8];
    const float* ln_gamma     = (const float*)d_in[9];
    const float* ln_beta      = (const float*)d_in[10];
    const float* W_scores     = (const float*)d_in[11];
    const float* b_scores     = (const float*)d_in[12];
    const float* W_hrs        = (const float*)d_in[13];
    const float* b_hrs        = (const float*)d_in[14];
    const float* W_info       = (const float*)d_in[15];
    const float* b_info       = (const float*)d_in[16];
    float* out = (float*)d_out;

    dim3 gi(Dn / 128, Bn / 8);
    kernel_info<<<gi, 128>>>(scores, oya, dora, hrs, oya_table, dora_table,
                             ln_gamma, ln_beta, W_scores, b_scores,
                             W_hrs, b_hrs, W_info, b_info);

    kernel_count<<<Bn, 128>>>(action);
    kernel_scan<<<1, Bn>>>();

    const int n4   = Bn * Sn * (Dn / 4);
    const int grid = n4 / (MAIN_TPB * MAIN_VPT);   // 16384
    kernel_main<<<grid, MAIN_TPB>>>(action, action_table, out);

    kernel_scatter<<<Bn, 128>>>(action, out);
}